// round 2
// baseline (speedup 1.0000x reference)
#include <cuda_runtime.h>
#include <math.h>

#define BATCH 256
#define SEQ   720
#define CH    321
#define CUTF  200
#define FOUT  400

typedef unsigned long long u64;

// packed fp32x2 FMA: d = a*b + d (per 32-bit lane)
__device__ __forceinline__ void fma2(u64& d, u64 a, u64 b) {
    asm("fma.rn.f32x2 %0, %1, %2, %0;" : "+l"(d) : "l"(a), "l"(b));
}
__device__ __forceinline__ float2 upk(u64 v) {
    float2 r;
    asm("mov.b64 {%0,%1}, %2;" : "=f"(r.x), "=f"(r.y) : "l"(v));
    return r;
}

// ---------------- scratch (__device__ globals, no allocation) ----------------
__device__ float d_Ecos[CUTF * SEQ];          // rfft cos table  [f][t]
__device__ float d_Esin[CUTF * SEQ];          // rfft sin table  [f][t]
__device__ float d_Fc[SEQ * FOUT];            // irfft cos coef  [t'][k] (scaled)
__device__ float d_Fs[SEQ * FOUT];            // irfft -sin coef [t'][k] (scaled)
__device__ float d_mean[BATCH * CH];
__device__ float d_stdev[BATCH * CH];
__device__ float d_invstd[BATCH * CH];
__device__ float d_xnT[(size_t)CH * SEQ * BATCH];   // [c][t][b]; reused for irfft output
__device__ float d_Xre[(size_t)CH * CUTF * BATCH];  // [c][f][b]
__device__ float d_Xim[(size_t)CH * CUTF * BATCH];
__device__ float d_Ore[(size_t)CH * FOUT * BATCH];  // [c][o][b]
__device__ float d_Oim[(size_t)CH * FOUT * BATCH];

// ---------------- twiddle tables (exact integer phase reduction) -------------
__global__ void k_init_tables() {
    int idx = blockIdx.x * 256 + threadIdx.x;
    if (idx < CUTF * SEQ) {
        int f = idx / SEQ, t = idx - f * SEQ;
        int r = (f * t) % SEQ;
        float s, c;
        sincospif((float)r * (1.0f / 360.0f), &s, &c);
        d_Ecos[idx] = c;
        d_Esin[idx] = s;
    }
    if (idx < SEQ * FOUT) {
        int tp = idx / FOUT, k = idx - tp * FOUT;
        int t = SEQ + tp;
        int m = (k * t) % 1440;
        float s, c;
        sincospif((float)m * (1.0f / 720.0f), &s, &c);
        d_Fc[idx] = (k == 0) ? (1.0f / 720.0f) : (c * (1.0f / 360.0f));
        d_Fs[idx] = (k == 0) ? 0.0f : (-s * (1.0f / 360.0f));
    }
}

// ---------------- per-(b,c) mean / stdev (ddof=1) ----------------------------
__global__ void k_stats(const float* __restrict__ x) {
    int c = blockIdx.x * 256 + threadIdx.x;
    int b = blockIdx.y;
    if (c >= CH) return;
    const float* p = x + (size_t)b * SEQ * CH + c;
    float s = 0.f, ss = 0.f;
    for (int t = 0; t < SEQ; t++) {
        float v = p[(size_t)t * CH];
        s += v;
        ss += v * v;
    }
    float mean = s * (1.0f / SEQ);
    float var = (ss - s * mean) * (1.0f / (SEQ - 1));
    float sd = sqrtf(var + 1e-5f);
    d_mean[b * CH + c] = mean;
    d_stdev[b * CH + c] = sd;
    d_invstd[b * CH + c] = 1.0f / sd;
}

// ---------------- transpose in: [b][t][c] -> [c][t][b], normalized -----------
__global__ void k_transpose_in(const float* __restrict__ x) {
    __shared__ float sm[32][33];
    int t = blockIdx.z;
    int cb = blockIdx.x * 32, bb = blockIdx.y * 32;
    int tx = threadIdx.x, ty = threadIdx.y;
    int c = cb + tx;
#pragma unroll
    for (int i = 0; i < 4; i++) {
        int b = bb + ty + i * 8;
        float v = 0.f;
        if (c < CH)
            v = (x[(size_t)b * (SEQ * CH) + t * CH + c] - d_mean[b * CH + c]) * d_invstd[b * CH + c];
        sm[ty + i * 8][tx] = v;
    }
    __syncthreads();
#pragma unroll
    for (int i = 0; i < 4; i++) {
        int cc = cb + ty + i * 8;
        if (cc < CH)
            d_xnT[(size_t)cc * (SEQ * BATCH) + t * BATCH + bb + tx] = sm[tx][ty + i * 8];
    }
}

// ---------------- stage 2: DFT (per channel, M=200 x2, N=256, K=720) ---------
// tile: 64 f x 128 b, thread: 4Mx8N, FMA2 inner loop, dup-A in shared.
__global__ __launch_bounds__(256) void k_dft() {
    const int c = blockIdx.z;
    const int fBase = blockIdx.y * 64;
    const int bBase = blockIdx.x * 128;
    __shared__ float sCd[16][128];   // dup cos pairs  [kk][2*m]
    __shared__ float sSd[16][128];   // dup (-sin) pairs
    __shared__ float sB[16][128];
    u64 accR[4][4] = {}, accI[4][4] = {};
    const int tid = threadIdx.x;
    const int tm = (tid >> 4) * 4;
    const int tn = (tid & 15) * 8;
    const float* xn = d_xnT + (size_t)c * (SEQ * BATCH);
    const int va_m = tid >> 2;            // 0..63
    const int va_k = (tid & 3) * 4;       // 0,4,8,12
    const int vb_k = tid >> 4;            // 0..15
    const int vb_n = (tid & 15) * 8;

    for (int k0 = 0; k0 < SEQ; k0 += 16) {
        float4 vc = {0, 0, 0, 0}, vs = {0, 0, 0, 0};
        int f = fBase + va_m;
        if (f < CUTF) {
            vc = *(const float4*)(d_Ecos + f * SEQ + k0 + va_k);
            vs = *(const float4*)(d_Esin + f * SEQ + k0 + va_k);
        }
        *(float2*)&sCd[va_k + 0][2 * va_m] = make_float2(vc.x, vc.x);
        *(float2*)&sCd[va_k + 1][2 * va_m] = make_float2(vc.y, vc.y);
        *(float2*)&sCd[va_k + 2][2 * va_m] = make_float2(vc.z, vc.z);
        *(float2*)&sCd[va_k + 3][2 * va_m] = make_float2(vc.w, vc.w);
        *(float2*)&sSd[va_k + 0][2 * va_m] = make_float2(-vs.x, -vs.x);
        *(float2*)&sSd[va_k + 1][2 * va_m] = make_float2(-vs.y, -vs.y);
        *(float2*)&sSd[va_k + 2][2 * va_m] = make_float2(-vs.z, -vs.z);
        *(float2*)&sSd[va_k + 3][2 * va_m] = make_float2(-vs.w, -vs.w);
        const float* brow = xn + (size_t)(k0 + vb_k) * BATCH + bBase + vb_n;
        *(float4*)&sB[vb_k][vb_n] = *(const float4*)brow;
        *(float4*)&sB[vb_k][vb_n + 4] = *(const float4*)(brow + 4);
        __syncthreads();
#pragma unroll
        for (int kk = 0; kk < 16; kk++) {
            ulonglong2 c01 = *(const ulonglong2*)&sCd[kk][2 * tm];
            ulonglong2 c23 = *(const ulonglong2*)&sCd[kk][2 * tm + 4];
            ulonglong2 s01 = *(const ulonglong2*)&sSd[kk][2 * tm];
            ulonglong2 s23 = *(const ulonglong2*)&sSd[kk][2 * tm + 4];
            ulonglong2 b01 = *(const ulonglong2*)&sB[kk][tn];
            ulonglong2 b23 = *(const ulonglong2*)&sB[kk][tn + 4];
            u64 ar[4] = {c01.x, c01.y, c23.x, c23.y};
            u64 ai[4] = {s01.x, s01.y, s23.x, s23.y};
            u64 bp[4] = {b01.x, b01.y, b23.x, b23.y};
#pragma unroll
            for (int i = 0; i < 4; i++)
#pragma unroll
                for (int j = 0; j < 4; j++) {
                    fma2(accR[i][j], ar[i], bp[j]);
                    fma2(accI[i][j], ai[i], bp[j]);
                }
        }
        __syncthreads();
    }
    float* Xr = d_Xre + (size_t)c * CUTF * BATCH;
    float* Xi = d_Xim + (size_t)c * CUTF * BATCH;
#pragma unroll
    for (int i = 0; i < 4; i++) {
        int f = fBase + tm + i;
        if (f < CUTF) {
            float2 r0 = upk(accR[i][0]), r1 = upk(accR[i][1]);
            float2 r2 = upk(accR[i][2]), r3 = upk(accR[i][3]);
            *(float4*)(Xr + f * BATCH + bBase + tn) = make_float4(r0.x, r0.y, r1.x, r1.y);
            *(float4*)(Xr + f * BATCH + bBase + tn + 4) = make_float4(r2.x, r2.y, r3.x, r3.y);
            float2 i0 = upk(accI[i][0]), i1 = upk(accI[i][1]);
            float2 i2 = upk(accI[i][2]), i3 = upk(accI[i][3]);
            *(float4*)(Xi + f * BATCH + bBase + tn) = make_float4(i0.x, i0.y, i1.x, i1.y);
            *(float4*)(Xi + f * BATCH + bBase + tn + 4) = make_float4(i2.x, i2.y, i3.x, i3.y);
        }
    }
}

// ---------------- stage 3: complex mixer (per channel, 400x256x200) ----------
// tile: 64 o x 128 b, thread: 4Mx8N, FMA2, dup-W (wr, wi, -wi) in shared.
__global__ __launch_bounds__(256) void k_cmul(const float* __restrict__ Wr,
                                              const float* __restrict__ Wi,
                                              const float* __restrict__ br,
                                              const float* __restrict__ bi) {
    const int c = blockIdx.z;
    const int oBase = blockIdx.y * 64;
    const int bBase = blockIdx.x * 128;
    __shared__ float sWr[8][128];   // dup wr
    __shared__ float sWi[8][128];   // dup wi
    __shared__ float sWn[8][128];   // dup -wi
    __shared__ float sXr[8][128];
    __shared__ float sXi[8][128];
    u64 accR[4][4] = {}, accI[4][4] = {};
    const int tid = threadIdx.x;
    const int tm = (tid >> 4) * 4;
    const int tn = (tid & 15) * 8;
    const float* wrp = Wr + (size_t)c * FOUT * CUTF;
    const float* wip = Wi + (size_t)c * FOUT * CUTF;
    const float* xrp = d_Xre + (size_t)c * CUTF * BATCH;
    const float* xip = d_Xim + (size_t)c * CUTF * BATCH;
    const int va_m = tid >> 2;          // 0..63
    const int va_k = (tid & 3) * 2;     // 0,2,4,6
    const int vb_k = tid >> 5;          // 0..7
    const int vb_n = (tid & 31) * 4;

    for (int k0 = 0; k0 < CUTF; k0 += 8) {
        int o = oBase + va_m;
        float2 w1 = {0, 0}, w2 = {0, 0};
        if (o < FOUT) {
            w1 = *(const float2*)(wrp + (size_t)o * CUTF + k0 + va_k);
            w2 = *(const float2*)(wip + (size_t)o * CUTF + k0 + va_k);
        }
        *(float2*)&sWr[va_k + 0][2 * va_m] = make_float2(w1.x, w1.x);
        *(float2*)&sWr[va_k + 1][2 * va_m] = make_float2(w1.y, w1.y);
        *(float2*)&sWi[va_k + 0][2 * va_m] = make_float2(w2.x, w2.x);
        *(float2*)&sWi[va_k + 1][2 * va_m] = make_float2(w2.y, w2.y);
        *(float2*)&sWn[va_k + 0][2 * va_m] = make_float2(-w2.x, -w2.x);
        *(float2*)&sWn[va_k + 1][2 * va_m] = make_float2(-w2.y, -w2.y);
        *(float4*)&sXr[vb_k][vb_n] = *(const float4*)(xrp + (k0 + vb_k) * BATCH + bBase + vb_n);
        *(float4*)&sXi[vb_k][vb_n] = *(const float4*)(xip + (k0 + vb_k) * BATCH + bBase + vb_n);
        __syncthreads();
#pragma unroll
        for (int kk = 0; kk < 8; kk++) {
            ulonglong2 r01 = *(const ulonglong2*)&sWr[kk][2 * tm];
            ulonglong2 r23 = *(const ulonglong2*)&sWr[kk][2 * tm + 4];
            ulonglong2 p01 = *(const ulonglong2*)&sWi[kk][2 * tm];
            ulonglong2 p23 = *(const ulonglong2*)&sWi[kk][2 * tm + 4];
            ulonglong2 n01 = *(const ulonglong2*)&sWn[kk][2 * tm];
            ulonglong2 n23 = *(const ulonglong2*)&sWn[kk][2 * tm + 4];
            ulonglong2 xr01 = *(const ulonglong2*)&sXr[kk][tn];
            ulonglong2 xr23 = *(const ulonglong2*)&sXr[kk][tn + 4];
            ulonglong2 xi01 = *(const ulonglong2*)&sXi[kk][tn];
            ulonglong2 xi23 = *(const ulonglong2*)&sXi[kk][tn + 4];
            u64 wr[4] = {r01.x, r01.y, r23.x, r23.y};
            u64 wi[4] = {p01.x, p01.y, p23.x, p23.y};
            u64 wn[4] = {n01.x, n01.y, n23.x, n23.y};
            u64 xr[4] = {xr01.x, xr01.y, xr23.x, xr23.y};
            u64 xi[4] = {xi01.x, xi01.y, xi23.x, xi23.y};
#pragma unroll
            for (int i = 0; i < 4; i++)
#pragma unroll
                for (int j = 0; j < 4; j++) {
                    fma2(accR[i][j], wr[i], xr[j]);
                    fma2(accR[i][j], wn[i], xi[j]);
                    fma2(accI[i][j], wr[i], xi[j]);
                    fma2(accI[i][j], wi[i], xr[j]);
                }
        }
        __syncthreads();
    }
    float* Or = d_Ore + (size_t)c * FOUT * BATCH;
    float* Oi = d_Oim + (size_t)c * FOUT * BATCH;
#pragma unroll
    for (int i = 0; i < 4; i++) {
        int o = oBase + tm + i;
        if (o < FOUT) {
            float vr = br[c * FOUT + o], vi = bi[c * FOUT + o];
            float2 r0 = upk(accR[i][0]), r1 = upk(accR[i][1]);
            float2 r2 = upk(accR[i][2]), r3 = upk(accR[i][3]);
            *(float4*)(Or + o * BATCH + bBase + tn) =
                make_float4(r0.x + vr, r0.y + vr, r1.x + vr, r1.y + vr);
            *(float4*)(Or + o * BATCH + bBase + tn + 4) =
                make_float4(r2.x + vr, r2.y + vr, r3.x + vr, r3.y + vr);
            float2 i0 = upk(accI[i][0]), i1 = upk(accI[i][1]);
            float2 i2 = upk(accI[i][2]), i3 = upk(accI[i][3]);
            *(float4*)(Oi + o * BATCH + bBase + tn) =
                make_float4(i0.x + vi, i0.y + vi, i1.x + vi, i1.y + vi);
            *(float4*)(Oi + o * BATCH + bBase + tn + 4) =
                make_float4(i2.x + vi, i2.y + vi, i3.x + vi, i3.y + vi);
        }
    }
}

// ---------------- stage 4: irfft tail (per channel, 720x256, K=400 re+im) ----
// tile: 64 t x 256 b, thread: 4Mx16N, FMA2, dup-F in shared.
__global__ __launch_bounds__(256) void k_irfft() {
    const int c = blockIdx.z;
    const int tBase = blockIdx.y * 64;
    __shared__ float sFc[8][128];   // dup Fc
    __shared__ float sFs[8][128];   // dup Fs (already has -sin & scale)
    __shared__ float sBr[8][256];
    __shared__ float sBi[8][256];
    u64 acc[4][8] = {};
    const int tid = threadIdx.x;
    const int tm = (tid >> 4) * 4;
    const int tn = (tid & 15) * 16;
    const float* orp = d_Ore + (size_t)c * FOUT * BATCH;
    const float* oip = d_Oim + (size_t)c * FOUT * BATCH;
    const int va_m = tid >> 2;          // 0..63
    const int va_k = (tid & 3) * 2;     // 0,2,4,6
    const int vb_k = tid >> 5;          // 0..7
    const int vb_n = (tid & 31) * 8;

    for (int k0 = 0; k0 < FOUT; k0 += 8) {
        int t = tBase + va_m;
        float2 f1 = {0, 0}, f2 = {0, 0};
        if (t < SEQ) {
            f1 = *(const float2*)(d_Fc + (size_t)t * FOUT + k0 + va_k);
            f2 = *(const float2*)(d_Fs + (size_t)t * FOUT + k0 + va_k);
        }
        *(float2*)&sFc[va_k + 0][2 * va_m] = make_float2(f1.x, f1.x);
        *(float2*)&sFc[va_k + 1][2 * va_m] = make_float2(f1.y, f1.y);
        *(float2*)&sFs[va_k + 0][2 * va_m] = make_float2(f2.x, f2.x);
        *(float2*)&sFs[va_k + 1][2 * va_m] = make_float2(f2.y, f2.y);
        const float* brow = orp + (size_t)(k0 + vb_k) * BATCH + vb_n;
        const float* irow = oip + (size_t)(k0 + vb_k) * BATCH + vb_n;
        *(float4*)&sBr[vb_k][vb_n] = *(const float4*)brow;
        *(float4*)&sBr[vb_k][vb_n + 4] = *(const float4*)(brow + 4);
        *(float4*)&sBi[vb_k][vb_n] = *(const float4*)irow;
        *(float4*)&sBi[vb_k][vb_n + 4] = *(const float4*)(irow + 4);
        __syncthreads();
#pragma unroll
        for (int kk = 0; kk < 8; kk++) {
            ulonglong2 c01 = *(const ulonglong2*)&sFc[kk][2 * tm];
            ulonglong2 c23 = *(const ulonglong2*)&sFc[kk][2 * tm + 4];
            ulonglong2 s01 = *(const ulonglong2*)&sFs[kk][2 * tm];
            ulonglong2 s23 = *(const ulonglong2*)&sFs[kk][2 * tm + 4];
            u64 fc[4] = {c01.x, c01.y, c23.x, c23.y};
            u64 fs[4] = {s01.x, s01.y, s23.x, s23.y};
            u64 bre[8], bim[8];
#pragma unroll
            for (int j = 0; j < 4; j++) {
                ulonglong2 rr = *(const ulonglong2*)&sBr[kk][tn + 4 * j];
                bre[2 * j] = rr.x; bre[2 * j + 1] = rr.y;
                ulonglong2 ii = *(const ulonglong2*)&sBi[kk][tn + 4 * j];
                bim[2 * j] = ii.x; bim[2 * j + 1] = ii.y;
            }
#pragma unroll
            for (int i = 0; i < 4; i++)
#pragma unroll
                for (int j = 0; j < 8; j++) {
                    fma2(acc[i][j], fc[i], bre[j]);
                    fma2(acc[i][j], fs[i], bim[j]);
                }
        }
        __syncthreads();
    }
    float* y = d_xnT + (size_t)c * SEQ * BATCH;
#pragma unroll
    for (int i = 0; i < 4; i++) {
        int t = tBase + tm + i;
        if (t < SEQ) {
#pragma unroll
            for (int j = 0; j < 4; j++) {
                float2 p0 = upk(acc[i][2 * j]), p1 = upk(acc[i][2 * j + 1]);
                *(float4*)(y + (size_t)t * BATCH + tn + 4 * j) =
                    make_float4(p0.x, p0.y, p1.x, p1.y);
            }
        }
    }
}

// ---------------- transpose out: [c][t][b] -> [b][t][c], de-normalize --------
__global__ void k_transpose_out(float* __restrict__ out) {
    __shared__ float sm[32][33];
    int t = blockIdx.z;
    int cb = blockIdx.x * 32, bb = blockIdx.y * 32;
    int tx = threadIdx.x, ty = threadIdx.y;
#pragma unroll
    for (int i = 0; i < 4; i++) {
        int cc = cb + ty + i * 8;
        float v = 0.f;
        if (cc < CH) v = d_xnT[(size_t)cc * (SEQ * BATCH) + t * BATCH + bb + tx];
        sm[ty + i * 8][tx] = v;
    }
    __syncthreads();
    int c = cb + tx;
#pragma unroll
    for (int i = 0; i < 4; i++) {
        int b = bb + ty + i * 8;
        if (c < CH) {
            float v = sm[tx][ty + i * 8];
            out[(size_t)b * (SEQ * CH) + t * CH + c] = v * d_stdev[b * CH + c] + d_mean[b * CH + c];
        }
    }
}

// ---------------- launch -----------------------------------------------------
extern "C" void kernel_launch(void* const* d_in, const int* in_sizes, int n_in,
                              void* d_out, int out_size) {
    const float* x_enc = (const float*)d_in[0];
    const float* Wr = (const float*)d_in[4];
    const float* Wi = (const float*)d_in[5];
    const float* br = (const float*)d_in[6];
    const float* bi = (const float*)d_in[7];
    float* out = (float*)d_out;

    k_init_tables<<<1125, 256>>>();
    k_stats<<<dim3(2, BATCH), 256>>>(x_enc);
    k_transpose_in<<<dim3(11, 8, SEQ), dim3(32, 8)>>>(x_enc);
    k_dft<<<dim3(2, 4, CH), 256>>>();
    k_cmul<<<dim3(2, 7, CH), 256>>>(Wr, Wi, br, bi);
    k_irfft<<<dim3(1, 12, CH), 256>>>();
    k_transpose_out<<<dim3(11, 8, SEQ), dim3(32, 8)>>>(out);
}

// round 3
// speedup vs baseline: 1.7152x; 1.7152x over previous
#include <cuda_runtime.h>
#include <math.h>

#define BATCH 256
#define SEQ   720
#define CH    321
#define CUTF  200
#define FOUT  400
#define FPAD  256
#define TPAD  768

typedef unsigned long long u64;

// packed fp32x2 FMA: d = a*b + d (per 32-bit lane)
__device__ __forceinline__ void fma2(u64& d, u64 a, u64 b) {
    asm("fma.rn.f32x2 %0, %1, %2, %0;" : "+l"(d) : "l"(a), "l"(b));
}
__device__ __forceinline__ u64 dupf(float a) {
    u64 r;
    unsigned int ai = __float_as_uint(a);
    asm("mov.b64 %0, {%1, %1};" : "=l"(r) : "r"(ai));
    return r;
}
__device__ __forceinline__ float2 upk(u64 v) {
    unsigned int lo, hi;
    asm("mov.b64 {%0, %1}, %2;" : "=r"(lo), "=r"(hi) : "l"(v));
    return make_float2(__uint_as_float(lo), __uint_as_float(hi));
}

// ---------------- scratch ----------------------------------------------------
__device__ float2 d_Epk[FPAD * SEQ];                 // (cos,-sin)[f][t], f padded
__device__ float2 d_Fpk[TPAD * FOUT];                // (Fc,Fs)[t'][k], t padded
__device__ float d_mean[BATCH * CH];
__device__ float d_stdev[BATCH * CH];
__device__ float d_invstd[BATCH * CH];
__device__ float d_xnT[(size_t)CH * SEQ * BATCH];    // [c][t][b]; reused for y
__device__ float2 d_Xc[(size_t)CH * CUTF * BATCH];   // interleaved (re,im) [c][f][b]
__device__ float2 d_Oc[(size_t)CH * FOUT * BATCH];   // interleaved (re,im) [c][o][b]

// ---------------- tables (exact integer phase reduction) ---------------------
__global__ void k_init_tables() {
    int idx = blockIdx.x * 256 + threadIdx.x;
    if (idx < FPAD * SEQ) {
        int f = idx / SEQ, t = idx - f * SEQ;
        float2 v = make_float2(0.f, 0.f);
        if (f < CUTF) {
            int r = (f * t) % SEQ;
            float s, c;
            sincospif((float)r * (1.0f / 360.0f), &s, &c);
            v = make_float2(c, -s);
        }
        d_Epk[idx] = v;
    }
    if (idx < TPAD * FOUT) {
        int tp = idx / FOUT, k = idx - tp * FOUT;
        float2 v = make_float2(0.f, 0.f);
        if (tp < SEQ) {
            int t = SEQ + tp;
            int m = (k * t) % 1440;
            float s, c;
            sincospif((float)m * (1.0f / 720.0f), &s, &c);
            v.x = (k == 0) ? (1.0f / 720.0f) : (c * (1.0f / 360.0f));
            v.y = (k == 0) ? 0.0f : (-s * (1.0f / 360.0f));
        }
        d_Fpk[idx] = v;
    }
}

// ---------------- per-(b,c) mean / stdev (ddof=1) ----------------------------
__global__ void k_stats(const float* __restrict__ x) {
    int c = blockIdx.x * 256 + threadIdx.x;
    int b = blockIdx.y;
    if (c >= CH) return;
    const float* p = x + (size_t)b * SEQ * CH + c;
    float s = 0.f, ss = 0.f;
    for (int t = 0; t < SEQ; t++) {
        float v = p[(size_t)t * CH];
        s += v;
        ss += v * v;
    }
    float mean = s * (1.0f / SEQ);
    float var = (ss - s * mean) * (1.0f / (SEQ - 1));
    float sd = sqrtf(var + 1e-5f);
    d_mean[b * CH + c] = mean;
    d_stdev[b * CH + c] = sd;
    d_invstd[b * CH + c] = 1.0f / sd;
}

// ---------------- transpose in: [b][t][c] -> [c][t][b], normalized -----------
__global__ void k_transpose_in(const float* __restrict__ x) {
    __shared__ float sm[32][33];
    int t = blockIdx.z;
    int cb = blockIdx.x * 32, bb = blockIdx.y * 32;
    int tx = threadIdx.x, ty = threadIdx.y;
    int c = cb + tx;
#pragma unroll
    for (int i = 0; i < 4; i++) {
        int b = bb + ty + i * 8;
        float v = 0.f;
        if (c < CH)
            v = (x[(size_t)b * (SEQ * CH) + t * CH + c] - d_mean[b * CH + c]) * d_invstd[b * CH + c];
        sm[ty + i * 8][tx] = v;
    }
    __syncthreads();
#pragma unroll
    for (int i = 0; i < 4; i++) {
        int cc = cb + ty + i * 8;
        if (cc < CH)
            d_xnT[(size_t)cc * (SEQ * BATCH) + t * BATCH + bb + tx] = sm[tx][ty + i * 8];
    }
}

// ---------------- stage 2: DFT (64f x 64b tile, acc lanes = (re,im)) ---------
__global__ __launch_bounds__(256) void k_dft() {
    const int c = blockIdx.z;
    const int fBase = blockIdx.y * 64;
    const int bBase = blockIdx.x * 64;
    __shared__ float2 sE[16][64];   // (cos,-sin), [k][f]
    __shared__ float sB[16][64];
    u64 acc[4][4] = {};             // [i: f][j: b], lanes (re,im)
    const int tid = threadIdx.x;
    const int tm = (tid >> 4) * 4;          // f group
    const int n0 = (tid & 15) * 2;          // b cols n0,n0+1,n0+32,n0+33
    const int le_f = tid >> 2, le_k = (tid & 3) * 4;
    const int lb_k = tid >> 4, lb_n = (tid & 15) * 4;
    const float2* Ep = d_Epk + (size_t)(fBase + le_f) * SEQ;
    const float* xn = d_xnT + (size_t)c * (SEQ * BATCH);

    for (int k0 = 0; k0 < SEQ; k0 += 16) {
        float4 e01 = *(const float4*)(Ep + k0 + le_k);
        float4 e23 = *(const float4*)(Ep + k0 + le_k + 2);
        sE[le_k + 0][le_f] = make_float2(e01.x, e01.y);
        sE[le_k + 1][le_f] = make_float2(e01.z, e01.w);
        sE[le_k + 2][le_f] = make_float2(e23.x, e23.y);
        sE[le_k + 3][le_f] = make_float2(e23.z, e23.w);
        *(float4*)&sB[lb_k][lb_n] =
            *(const float4*)(xn + (size_t)(k0 + lb_k) * BATCH + bBase + lb_n);
        __syncthreads();
#pragma unroll
        for (int kk = 0; kk < 16; kk++) {
            ulonglong2 a01 = *(const ulonglong2*)&sE[kk][tm];
            ulonglong2 a23 = *(const ulonglong2*)&sE[kk][tm + 2];
            float2 p = *(const float2*)&sB[kk][n0];
            float2 q = *(const float2*)&sB[kk][n0 + 32];
            u64 a[4] = {a01.x, a01.y, a23.x, a23.y};
            u64 bb[4] = {dupf(p.x), dupf(p.y), dupf(q.x), dupf(q.y)};
#pragma unroll
            for (int i = 0; i < 4; i++)
#pragma unroll
                for (int j = 0; j < 4; j++)
                    fma2(acc[i][j], a[i], bb[j]);
        }
        __syncthreads();
    }
#pragma unroll
    for (int i = 0; i < 4; i++) {
        int f = fBase + tm + i;
        if (f < CUTF) {
            float2* row = d_Xc + ((size_t)c * CUTF + f) * BATCH + bBase;
            ulonglong2 v0; v0.x = acc[i][0]; v0.y = acc[i][1];
            ulonglong2 v1; v1.x = acc[i][2]; v1.y = acc[i][3];
            *(ulonglong2*)(row + n0) = v0;
            *(ulonglong2*)(row + n0 + 32) = v1;
        }
    }
}

// ---------------- stage 3: complex mixer (64o x 64b tile) --------------------
__global__ __launch_bounds__(256) void k_cmul(const float* __restrict__ Wr,
                                              const float* __restrict__ Wi,
                                              const float* __restrict__ br,
                                              const float* __restrict__ bi) {
    const int c = blockIdx.z;
    const int oBase = blockIdx.y * 64;
    const int bBase = blockIdx.x * 64;
    __shared__ float2 sWrr[8][64];  // (wr,wr)
    __shared__ float2 sWni[8][64];  // (-wi,wi)
    __shared__ float2 sX[8][64];    // (xr,xi)
    __shared__ float2 sXs[8][64];   // (xi,xr)
    u64 acc[4][4] = {};             // lanes (Or,Oi)
    const int tid = threadIdx.x;
    const int tm = (tid >> 4) * 4;
    const int n0 = (tid & 15) * 2;
    const int lw_o = tid >> 2, lw_k = (tid & 3) * 2;
    const int lx_k = tid >> 5, lx_n = (tid & 31) * 2;
    const float* wrp = Wr + (size_t)c * FOUT * CUTF;
    const float* wip = Wi + (size_t)c * FOUT * CUTF;
    const float2* Xrow = d_Xc + (size_t)c * CUTF * BATCH;

    for (int k0 = 0; k0 < CUTF; k0 += 8) {
        int o = oBase + lw_o;
        float2 w1 = make_float2(0.f, 0.f), w2 = make_float2(0.f, 0.f);
        if (o < FOUT) {
            w1 = *(const float2*)(wrp + (size_t)o * CUTF + k0 + lw_k);
            w2 = *(const float2*)(wip + (size_t)o * CUTF + k0 + lw_k);
        }
        sWrr[lw_k + 0][lw_o] = make_float2(w1.x, w1.x);
        sWrr[lw_k + 1][lw_o] = make_float2(w1.y, w1.y);
        sWni[lw_k + 0][lw_o] = make_float2(-w2.x, w2.x);
        sWni[lw_k + 1][lw_o] = make_float2(-w2.y, w2.y);
        float4 xv = *(const float4*)(Xrow + (size_t)(k0 + lx_k) * BATCH + bBase + lx_n);
        sX[lx_k][lx_n] = make_float2(xv.x, xv.y);
        sX[lx_k][lx_n + 1] = make_float2(xv.z, xv.w);
        sXs[lx_k][lx_n] = make_float2(xv.y, xv.x);
        sXs[lx_k][lx_n + 1] = make_float2(xv.w, xv.z);
        __syncthreads();
#pragma unroll
        for (int kk = 0; kk < 8; kk++) {
            ulonglong2 r01 = *(const ulonglong2*)&sWrr[kk][tm];
            ulonglong2 r23 = *(const ulonglong2*)&sWrr[kk][tm + 2];
            ulonglong2 n01 = *(const ulonglong2*)&sWni[kk][tm];
            ulonglong2 n23 = *(const ulonglong2*)&sWni[kk][tm + 2];
            ulonglong2 x01 = *(const ulonglong2*)&sX[kk][n0];
            ulonglong2 x23 = *(const ulonglong2*)&sX[kk][n0 + 32];
            ulonglong2 s01 = *(const ulonglong2*)&sXs[kk][n0];
            ulonglong2 s23 = *(const ulonglong2*)&sXs[kk][n0 + 32];
            u64 wrr[4] = {r01.x, r01.y, r23.x, r23.y};
            u64 wni[4] = {n01.x, n01.y, n23.x, n23.y};
            u64 xx[4] = {x01.x, x01.y, x23.x, x23.y};
            u64 xs[4] = {s01.x, s01.y, s23.x, s23.y};
#pragma unroll
            for (int i = 0; i < 4; i++)
#pragma unroll
                for (int j = 0; j < 4; j++) {
                    fma2(acc[i][j], wrr[i], xx[j]);
                    fma2(acc[i][j], wni[i], xs[j]);
                }
        }
        __syncthreads();
    }
#pragma unroll
    for (int i = 0; i < 4; i++) {
        int o = oBase + tm + i;
        if (o < FOUT) {
            float vr = br[c * FOUT + o], vi = bi[c * FOUT + o];
            float2* row = d_Oc + ((size_t)c * FOUT + o) * BATCH + bBase;
            float2 a0 = upk(acc[i][0]), a1 = upk(acc[i][1]);
            float2 a2 = upk(acc[i][2]), a3 = upk(acc[i][3]);
            *(float4*)(row + n0) = make_float4(a0.x + vr, a0.y + vi, a1.x + vr, a1.y + vi);
            *(float4*)(row + n0 + 32) = make_float4(a2.x + vr, a2.y + vi, a3.x + vr, a3.y + vi);
        }
    }
}

// ---------------- stage 4: irfft tail (64t x 64b tile) -----------------------
__global__ __launch_bounds__(256) void k_irfft() {
    const int c = blockIdx.z;
    const int tBase = blockIdx.y * 64;
    const int bBase = blockIdx.x * 64;
    __shared__ float2 sF[8][64];    // (Fc,Fs), [k][t]
    __shared__ float2 sO[8][64];    // (Or,Oi)
    u64 acc[4][4] = {};
    const int tid = threadIdx.x;
    const int tm = (tid >> 4) * 4;
    const int n0 = (tid & 15) * 2;
    const int lf_t = tid >> 2, lf_k = (tid & 3) * 2;
    const int lo_k = tid >> 5, lo_n = (tid & 31) * 2;
    const float2* Fp = d_Fpk + (size_t)(tBase + lf_t) * FOUT;
    const float2* Orow = d_Oc + (size_t)c * FOUT * BATCH;

    for (int k0 = 0; k0 < FOUT; k0 += 8) {
        float4 fv = *(const float4*)(Fp + k0 + lf_k);
        sF[lf_k + 0][lf_t] = make_float2(fv.x, fv.y);
        sF[lf_k + 1][lf_t] = make_float2(fv.z, fv.w);
        float4 ov = *(const float4*)(Orow + (size_t)(k0 + lo_k) * BATCH + bBase + lo_n);
        sO[lo_k][lo_n] = make_float2(ov.x, ov.y);
        sO[lo_k][lo_n + 1] = make_float2(ov.z, ov.w);
        __syncthreads();
#pragma unroll
        for (int kk = 0; kk < 8; kk++) {
            ulonglong2 f01 = *(const ulonglong2*)&sF[kk][tm];
            ulonglong2 f23 = *(const ulonglong2*)&sF[kk][tm + 2];
            ulonglong2 o01 = *(const ulonglong2*)&sO[kk][n0];
            ulonglong2 o23 = *(const ulonglong2*)&sO[kk][n0 + 32];
            u64 ff[4] = {f01.x, f01.y, f23.x, f23.y};
            u64 oo[4] = {o01.x, o01.y, o23.x, o23.y};
#pragma unroll
            for (int i = 0; i < 4; i++)
#pragma unroll
                for (int j = 0; j < 4; j++)
                    fma2(acc[i][j], ff[i], oo[j]);
        }
        __syncthreads();
    }
    float* y = d_xnT + (size_t)c * SEQ * BATCH;
#pragma unroll
    for (int i = 0; i < 4; i++) {
        int t = tBase + tm + i;
        if (t < SEQ) {
            float2 a0 = upk(acc[i][0]), a1 = upk(acc[i][1]);
            float2 a2 = upk(acc[i][2]), a3 = upk(acc[i][3]);
            *(float2*)(y + (size_t)t * BATCH + bBase + n0) =
                make_float2(a0.x + a0.y, a1.x + a1.y);
            *(float2*)(y + (size_t)t * BATCH + bBase + n0 + 32) =
                make_float2(a2.x + a2.y, a3.x + a3.y);
        }
    }
}

// ---------------- transpose out: [c][t][b] -> [b][t][c], de-normalize --------
__global__ void k_transpose_out(float* __restrict__ out) {
    __shared__ float sm[32][33];
    int t = blockIdx.z;
    int cb = blockIdx.x * 32, bb = blockIdx.y * 32;
    int tx = threadIdx.x, ty = threadIdx.y;
#pragma unroll
    for (int i = 0; i < 4; i++) {
        int cc = cb + ty + i * 8;
        float v = 0.f;
        if (cc < CH) v = d_xnT[(size_t)cc * (SEQ * BATCH) + t * BATCH + bb + tx];
        sm[ty + i * 8][tx] = v;
    }
    __syncthreads();
    int c = cb + tx;
#pragma unroll
    for (int i = 0; i < 4; i++) {
        int b = bb + ty + i * 8;
        if (c < CH) {
            float v = sm[tx][ty + i * 8];
            out[(size_t)b * (SEQ * CH) + t * CH + c] = v * d_stdev[b * CH + c] + d_mean[b * CH + c];
        }
    }
}

// ---------------- launch -----------------------------------------------------
extern "C" void kernel_launch(void* const* d_in, const int* in_sizes, int n_in,
                              void* d_out, int out_size) {
    const float* x_enc = (const float*)d_in[0];
    const float* Wr = (const float*)d_in[4];
    const float* Wi = (const float*)d_in[5];
    const float* br = (const float*)d_in[6];
    const float* bi = (const float*)d_in[7];
    float* out = (float*)d_out;

    k_init_tables<<<1200, 256>>>();
    k_stats<<<dim3(2, BATCH), 256>>>(x_enc);
    k_transpose_in<<<dim3(11, 8, SEQ), dim3(32, 8)>>>(x_enc);
    k_dft<<<dim3(4, 4, CH), 256>>>();
    k_cmul<<<dim3(4, 7, CH), 256>>>(Wr, Wi, br, bi);
    k_irfft<<<dim3(4, 12, CH), 256>>>();
    k_transpose_out<<<dim3(11, 8, SEQ), dim3(32, 8)>>>(out);
}

// round 6
// speedup vs baseline: 4.1679x; 2.4300x over previous
#include <cuda_runtime.h>
#include <cuda_bf16.h>
#include <math.h>
#include <stdint.h>

#define BATCH 256
#define SEQ   720
#define CH    321
#define CUTF  200
#define FOUT  400

#define KD 768    // padded K stage1 (time 720)
#define KX 448    // padded K stage2 (2*CUTF=400)
#define KO 832    // padded K stage3 (2*FOUT=800)
#define N1 512    // padded N stage1
#define N3 768    // padded N stage3

#define RSB 80            // smem row stride bytes (32 bf16 + 8 pad)
#define TB  (128 * RSB)   // one tile: 10240 B
#define SMEM_BYTES (8 * TB)  // 2 buffers x 4 tiles = 81920

typedef unsigned int u32;
typedef uint16_t u16;

// ---------------- device scratch ---------------------------------------------
__device__ __align__(256) __nv_bfloat16 d_Eh[(size_t)N1 * KD];
__device__ __align__(256) __nv_bfloat16 d_El[(size_t)N1 * KD];
__device__ __align__(256) __nv_bfloat16 d_Fh[(size_t)N3 * KO];
__device__ __align__(256) __nv_bfloat16 d_Fl[(size_t)N3 * KO];
__device__ __align__(256) __nv_bfloat16 d_xnh[(size_t)CH * BATCH * KD];
__device__ __align__(256) __nv_bfloat16 d_xnl[(size_t)CH * BATCH * KD];
__device__ __align__(256) __nv_bfloat16 d_Xh[(size_t)CH * BATCH * KX];
__device__ __align__(256) __nv_bfloat16 d_Xl[(size_t)CH * BATCH * KX];
__device__ __align__(256) __nv_bfloat16 d_Oh[(size_t)CH * BATCH * KO];
__device__ __align__(256) __nv_bfloat16 d_Ol[(size_t)CH * BATCH * KO];
__device__ __align__(256) float d_y[(size_t)CH * BATCH * SEQ];
__device__ float d_mean[BATCH * CH];
__device__ float d_stdev[BATCH * CH];
__device__ float d_invstd[BATCH * CH];

// ---------------- helpers ----------------------------------------------------
__device__ __forceinline__ u32 s2u(const void* p) {
    u32 a;
    asm("{ .reg .u64 t; cvta.to.shared.u64 t, %1; cvt.u32.u64 %0, t; }" : "=r"(a) : "l"(p));
    return a;
}
__device__ __forceinline__ void cpa16(u32 dst, const void* src) {
    asm volatile("cp.async.ca.shared.global [%0], [%1], 16;" :: "r"(dst), "l"(src));
}
__device__ __forceinline__ void cp_commit() {
    asm volatile("cp.async.commit_group;");
}
__device__ __forceinline__ void cp_wait1() {
    asm volatile("cp.async.wait_group 1;");
}
__device__ __forceinline__ void cp_wait0() {
    asm volatile("cp.async.wait_group 0;");
}
__device__ __forceinline__ void ldsm4(u32 a[4], u32 addr) {
    asm volatile("ldmatrix.sync.aligned.m8n8.x4.shared.b16 {%0,%1,%2,%3}, [%4];"
                 : "=r"(a[0]), "=r"(a[1]), "=r"(a[2]), "=r"(a[3]) : "r"(addr));
}
__device__ __forceinline__ void mma16816(float c[4], const u32 a[4], u32 b0, u32 b1) {
    asm volatile(
        "mma.sync.aligned.m16n8k16.row.col.f32.bf16.bf16.f32 "
        "{%0,%1,%2,%3},{%4,%5,%6,%7},{%8,%9},{%0,%1,%2,%3};"
        : "+f"(c[0]), "+f"(c[1]), "+f"(c[2]), "+f"(c[3])
        : "r"(a[0]), "r"(a[1]), "r"(a[2]), "r"(a[3]), "r"(b0), "r"(b1));
}
__device__ __forceinline__ void hilo(float v, u16& h, u16& l) {
    __nv_bfloat16 hb = __float2bfloat16_rn(v);
    __nv_bfloat16 lb = __float2bfloat16_rn(v - __bfloat162float(hb));
    h = __bfloat16_as_ushort(hb);
    l = __bfloat16_as_ushort(lb);
}

// cp.async one 128x32bf16 tile (64B/row) into padded smem
__device__ __forceinline__ void cp_tile(u32 smDst, const char* gSrc, int rowStrideBytes,
                                        int kByteOff, int tid) {
    int row = tid >> 1, seg = (tid & 1) * 32;
    const char* s = gSrc + (size_t)row * rowStrideBytes + kByteOff + seg;
    u32 d = smDst + row * RSB + seg;
    cpa16(d, s);
    cpa16(d + 16, s + 16);
}

// one 32-K chunk of HMMA on a 128x128 tile (8 warps 2x4, warp 64x32)
__device__ __forceinline__ void compute_chunk(float acc[4][4][4], u32 ah_b, u32 al_b,
                                              u32 bh_b, u32 bl_b, int wm, int wn, int lane) {
    const int rsel = lane & 15;
    const int kbh = (lane >> 4) * 16;
#pragma unroll
    for (int k16 = 0; k16 < 2; k16++) {
        int kb = k16 * 32 + kbh;
        u32 bh[2][4], bl[2][4];
#pragma unroll
        for (int np = 0; np < 2; np++) {
            u32 off = (u32)(wn * 32 + np * 16 + rsel) * RSB + kb;
            ldsm4(bh[np], bh_b + off);
            ldsm4(bl[np], bl_b + off);
        }
#pragma unroll
        for (int mt = 0; mt < 4; mt++) {
            u32 off = (u32)(wm * 64 + mt * 16 + rsel) * RSB + kb;
            u32 ah[4], al[4];
            ldsm4(ah, ah_b + off);
            ldsm4(al, al_b + off);
#pragma unroll
            for (int nt = 0; nt < 4; nt++) {
                u32 b0h = bh[nt >> 1][nt & 1], b1h = bh[nt >> 1][(nt & 1) + 2];
                u32 b0l = bl[nt >> 1][nt & 1], b1l = bl[nt >> 1][(nt & 1) + 2];
                mma16816(acc[mt][nt], ah, b0h, b1h);
                mma16816(acc[mt][nt], ah, b0l, b1l);
                mma16816(acc[mt][nt], al, b0h, b1h);
            }
        }
    }
}

// ---------------- table init -------------------------------------------------
__global__ void k_init() {
    int idx = blockIdx.x * 256 + threadIdx.x;
    if (idx < CUTF * SEQ) {
        int f = idx / SEQ, t = idx - f * SEQ;
        int r = (f * t) % SEQ;
        float s, cc;
        sincospif((float)r * (1.0f / 360.0f), &s, &cc);
        size_t i0 = (size_t)(2 * f) * KD + t;
        size_t i1 = (size_t)(2 * f + 1) * KD + t;
        u16 h, l;
        hilo(cc, h, l);  d_Eh[i0] = __ushort_as_bfloat16(h); d_El[i0] = __ushort_as_bfloat16(l);
        hilo(-s, h, l);  d_Eh[i1] = __ushort_as_bfloat16(h); d_El[i1] = __ushort_as_bfloat16(l);
    }
    if (idx < SEQ * FOUT) {
        int tp = idx / FOUT, k = idx - tp * FOUT;
        int t = SEQ + tp;
        int m = (k * t) % 1440;
        float s, cc;
        sincospif((float)m * (1.0f / 720.0f), &s, &cc);
        float fc = (k == 0) ? (1.0f / 720.0f) : (cc * (1.0f / 360.0f));
        float fs = (k == 0) ? 0.0f : (-s * (1.0f / 360.0f));
        size_t i0 = (size_t)tp * KO + 2 * k;
        u16 h, l;
        hilo(fc, h, l); d_Fh[i0] = __ushort_as_bfloat16(h); d_Fl[i0] = __ushort_as_bfloat16(l);
        hilo(fs, h, l); d_Fh[i0 + 1] = __ushort_as_bfloat16(h); d_Fl[i0 + 1] = __ushort_as_bfloat16(l);
    }
}

// ---------------- stats ------------------------------------------------------
__global__ void k_stats(const float* __restrict__ x) {
    int c = blockIdx.x * 256 + threadIdx.x;
    int b = blockIdx.y;
    if (c >= CH) return;
    const float* p = x + (size_t)b * SEQ * CH + c;
    float s = 0.f, ss = 0.f;
    for (int t = 0; t < SEQ; t++) {
        float v = p[(size_t)t * CH];
        s += v;
        ss += v * v;
    }
    float mean = s * (1.0f / SEQ);
    float var = (ss - s * mean) * (1.0f / (SEQ - 1));
    float sd = sqrtf(var + 1e-5f);
    d_mean[b * CH + c] = mean;
    d_stdev[b * CH + c] = sd;
    d_invstd[b * CH + c] = 1.0f / sd;
}

// ---------------- transpose in: x[b][t][c] -> xn[c][b][t] bf16 hi/lo ---------
__global__ void k_transpose_in(const float* __restrict__ x) {
    __shared__ float sm[32][33];
    int b = blockIdx.z;
    int c0 = blockIdx.x * 32, t0 = blockIdx.y * 32;
    int tx = threadIdx.x, ty = threadIdx.y;
#pragma unroll
    for (int i = 0; i < 4; i++) {
        int t = t0 + ty + i * 8, c = c0 + tx;
        float v = 0.f;
        if (c < CH && t < SEQ)
            v = (x[(size_t)b * SEQ * CH + (size_t)t * CH + c] - d_mean[b * CH + c]) * d_invstd[b * CH + c];
        sm[ty + i * 8][tx] = v;
    }
    __syncthreads();
#pragma unroll
    for (int i = 0; i < 4; i++) {
        int c = c0 + ty + i * 8;
        int t = t0 + tx;
        if (c < CH && t < SEQ) {
            float v = sm[tx][ty + i * 8];
            u16 h, l;
            hilo(v, h, l);
            size_t idx = ((size_t)c * BATCH + b) * KD + t;
            d_xnh[idx] = __ushort_as_bfloat16(h);
            d_xnl[idx] = __ushort_as_bfloat16(l);
        }
    }
}

// ---------------- stage 1: DFT GEMM ------------------------------------------
#define NCH1 23
__global__ __launch_bounds__(256, 2) void k_g1() {
    extern __shared__ char smraw[];
    u32 smb = s2u(smraw);
    const int tid = threadIdx.x, lane = tid & 31, warp = tid >> 5;
    const int wm = warp >> 2, wn = warp & 3;
    const int cidx = blockIdx.z, mBase = blockIdx.y * 128, nBase = blockIdx.x * 128;
    const char* gAh = (const char*)(d_xnh + ((size_t)cidx * BATCH + mBase) * KD);
    const char* gAl = (const char*)(d_xnl + ((size_t)cidx * BATCH + mBase) * KD);
    const char* gBh = (const char*)(d_Eh + (size_t)nBase * KD);
    const char* gBl = (const char*)(d_El + (size_t)nBase * KD);
    float acc[4][4][4] = {};

    cp_tile(smb + 0 * TB, gAh, KD * 2, 0, tid);
    cp_tile(smb + 1 * TB, gAl, KD * 2, 0, tid);
    cp_tile(smb + 2 * TB, gBh, KD * 2, 0, tid);
    cp_tile(smb + 3 * TB, gBl, KD * 2, 0, tid);
    cp_commit();
    for (int ch = 0; ch < NCH1; ch++) {
        u32 buf = smb + (ch & 1) * 4 * TB;
        if (ch + 1 < NCH1) {
            u32 nb = smb + ((ch + 1) & 1) * 4 * TB;
            int kb = (ch + 1) * 64;
            cp_tile(nb + 0 * TB, gAh, KD * 2, kb, tid);
            cp_tile(nb + 1 * TB, gAl, KD * 2, kb, tid);
            cp_tile(nb + 2 * TB, gBh, KD * 2, kb, tid);
            cp_tile(nb + 3 * TB, gBl, KD * 2, kb, tid);
            cp_commit();
            cp_wait1();
        } else {
            cp_wait0();
        }
        __syncthreads();
        compute_chunk(acc, buf, buf + TB, buf + 2 * TB, buf + 3 * TB, wm, wn, lane);
        __syncthreads();
    }
    const int g = lane >> 2, iq = lane & 3;
#pragma unroll
    for (int mt = 0; mt < 4; mt++) {
        int row = mBase + wm * 64 + mt * 16 + g;
        size_t b0 = ((size_t)cidx * BATCH + row) * KX;
        size_t b1 = b0 + 8 * (size_t)KX;
#pragma unroll
        for (int nt = 0; nt < 4; nt++) {
            int col = nBase + wn * 32 + nt * 8 + 2 * iq;
            if (col < 400) {
                float* cc = acc[mt][nt];
                u16 h0, l0, h1, l1;
                hilo(cc[0], h0, l0); hilo(cc[1], h1, l1);
                *(u32*)(d_Xh + b0 + col) = (u32)h0 | ((u32)h1 << 16);
                *(u32*)(d_Xl + b0 + col) = (u32)l0 | ((u32)l1 << 16);
                hilo(cc[2], h0, l0); hilo(cc[3], h1, l1);
                *(u32*)(d_Xh + b1 + col) = (u32)h0 | ((u32)h1 << 16);
                *(u32*)(d_Xl + b1 + col) = (u32)l0 | ((u32)l1 << 16);
            }
        }
    }
}

// ---------------- stage 2: complex mixer GEMM --------------------------------
// build W2 chunk (128 o2-rows x 32 k2-cols) into smem bf16 hi/lo tiles
__device__ __forceinline__ void build_w2(const float* __restrict__ Wr,
                                         const float* __restrict__ Wi,
                                         int cidx, int nBase, int chunk,
                                         u32 Bh, u32 Bl, int tid) {
    int oloc = tid >> 2;            // 0..63
    int part = tid & 3;             // 4 f values
    int o = ((nBase >> 1) + oloc);
    int f0 = chunk * 16 + part * 4;
    float a0 = 0.f, a1 = 0.f, a2 = 0.f, a3 = 0.f;
    float q0 = 0.f, q1 = 0.f, q2 = 0.f, q3 = 0.f;
    if (o < FOUT && f0 + 3 < CUTF) {
        const float4 wr4 = *(const float4*)(Wr + ((size_t)cidx * FOUT + o) * CUTF + f0);
        const float4 wi4 = *(const float4*)(Wi + ((size_t)cidx * FOUT + o) * CUTF + f0);
        a0 = wr4.x; a1 = wr4.y; a2 = wr4.z; a3 = wr4.w;
        q0 = wi4.x; q1 = wi4.y; q2 = wi4.z; q3 = wi4.w;
    }
    float av[4] = {a0, a1, a2, a3};
    float qv[4] = {q0, q1, q2, q3};
    u32 he[4], le[4], ho[4], lo[4];   // even row / odd row packed pairs
#pragma unroll
    for (int j = 0; j < 4; j++) {
        u16 h0, l0, h1, l1;
        hilo(av[j], h0, l0); hilo(-qv[j], h1, l1);         // even row: (wr, -wi)
        he[j] = (u32)h0 | ((u32)h1 << 16);
        le[j] = (u32)l0 | ((u32)l1 << 16);
        hilo(qv[j], h0, l0); hilo(av[j], h1, l1);          // odd row: (wi, wr)
        ho[j] = (u32)h0 | ((u32)h1 << 16);
        lo[j] = (u32)l0 | ((u32)l1 << 16);
    }
    u32 offE = (u32)(2 * oloc) * RSB + part * 16;
    u32 offO = offE + RSB;
    *(uint4*)(size_t)0;  // (placeholder removed below)
    // store
    asm volatile("st.shared.v4.b32 [%0], {%1,%2,%3,%4};" :: "r"(Bh + offE), "r"(he[0]), "r"(he[1]), "r"(he[2]), "r"(he[3]));
    asm volatile("st.shared.v4.b32 [%0], {%1,%2,%3,%4};" :: "r"(Bl + offE), "r"(le[0]), "r"(le[1]), "r"(le[2]), "r"(le[3]));
    asm volatile("st.shared.v4.b32 [%0], {%1,%2,%3,%4};" :: "r"(Bh + offO), "r"(ho[0]), "r"(ho[1]), "r"(ho[2]), "r"(ho[3]));
    asm volatile("st.shared.v4.b32 [%0], {%1,%2,%3,%4};" :: "r"(Bl + offO), "r"(lo[0]), "r"(lo[1]), "r"(lo[2]), "r"(lo[3]));
}

#define NCH2 13
__global__ __launch_bounds__(256, 2) void k_g2(const float* __restrict__ Wr,
                                               const float* __restrict__ Wi,
                                               const float* __restrict__ br,
                                               const float* __restrict__ bi) {
    extern __shared__ char smraw[];
    u32 smb = s2u(smraw);
    const int tid = threadIdx.x, lane = tid & 31, warp = tid >> 5;
    const int wm = warp >> 2, wn = warp & 3;
    const int cidx = blockIdx.z, mBase = blockIdx.y * 128, nBase = blockIdx.x * 128;
    const char* gAh = (const char*)(d_Xh + ((size_t)cidx * BATCH + mBase) * KX);
    const char* gAl = (const char*)(d_Xl + ((size_t)cidx * BATCH + mBase) * KX);
    float acc[4][4][4] = {};

    cp_tile(smb + 0 * TB, gAh, KX * 2, 0, tid);
    cp_tile(smb + 1 * TB, gAl, KX * 2, 0, tid);
    cp_commit();
    build_w2(Wr, Wi, cidx, nBase, 0, smb + 2 * TB, smb + 3 * TB, tid);
    for (int ch = 0; ch < NCH2; ch++) {
        u32 buf = smb + (ch & 1) * 4 * TB;
        if (ch + 1 < NCH2) {
            u32 nb = smb + ((ch + 1) & 1) * 4 * TB;
            int kb = (ch + 1) * 64;
            cp_tile(nb + 0 * TB, gAh, KX * 2, kb, tid);
            cp_tile(nb + 1 * TB, gAl, KX * 2, kb, tid);
            cp_commit();
            build_w2(Wr, Wi, cidx, nBase, ch + 1, nb + 2 * TB, nb + 3 * TB, tid);
            cp_wait1();
        } else {
            cp_wait0();
        }
        __syncthreads();
        compute_chunk(acc, buf, buf + TB, buf + 2 * TB, buf + 3 * TB, wm, wn, lane);
        __syncthreads();
    }
    const int g = lane >> 2, iq = lane & 3;
    const float* brp = br + (size_t)cidx * FOUT;
    const float* bip = bi + (size_t)cidx * FOUT;
#pragma unroll
    for (int mt = 0; mt < 4; mt++) {
        int row = mBase + wm * 64 + mt * 16 + g;
        size_t b0 = ((size_t)cidx * BATCH + row) * KO;
        size_t b1 = b0 + 8 * (size_t)KO;
#pragma unroll
        for (int nt = 0; nt < 4; nt++) {
            int col = nBase + wn * 32 + nt * 8 + 2 * iq;
            if (col < 800) {
                int o = col >> 1;
                float vr = brp[o], vi = bip[o];
                float* cc = acc[mt][nt];
                u16 h0, l0, h1, l1;
                hilo(cc[0] + vr, h0, l0); hilo(cc[1] + vi, h1, l1);
                *(u32*)(d_Oh + b0 + col) = (u32)h0 | ((u32)h1 << 16);
                *(u32*)(d_Ol + b0 + col) = (u32)l0 | ((u32)l1 << 16);
                hilo(cc[2] + vr, h0, l0); hilo(cc[3] + vi, h1, l1);
                *(u32*)(d_Oh + b1 + col) = (u32)h0 | ((u32)h1 << 16);
                *(u32*)(d_Ol + b1 + col) = (u32)l0 | ((u32)l1 << 16);
            }
        }
    }
}

// ---------------- stage 3: irfft GEMM ----------------------------------------
#define NCH3 25
__global__ __launch_bounds__(256, 2) void k_g3() {
    extern __shared__ char smraw[];
    u32 smb = s2u(smraw);
    const int tid = threadIdx.x, lane = tid & 31, warp = tid >> 5;
    const int wm = warp >> 2, wn = warp & 3;
    const int cidx = blockIdx.z, mBase = blockIdx.y * 128, nBase = blockIdx.x * 128;
    const char* gAh = (const char*)(d_Oh + ((size_t)cidx * BATCH + mBase) * KO);
    const char* gAl = (const char*)(d_Ol + ((size_t)cidx * BATCH + mBase) * KO);
    const char* gBh = (const char*)(d_Fh + (size_t)nBase * KO);
    const char* gBl = (const char*)(d_Fl + (size_t)nBase * KO);
    float acc[4][4][4] = {};

    cp_tile(smb + 0 * TB, gAh, KO * 2, 0, tid);
    cp_tile(smb + 1 * TB, gAl, KO * 2, 0, tid);
    cp_tile(smb + 2 * TB, gBh, KO * 2, 0, tid);
    cp_tile(smb + 3 * TB, gBl, KO * 2, 0, tid);
    cp_commit();
    for (int ch = 0; ch < NCH3; ch++) {
        u32 buf = smb + (ch & 1) * 4 * TB;
        if (ch + 1 < NCH3) {
            u32 nb = smb + ((ch + 1) & 1) * 4 * TB;
            int kb = (ch + 1) * 64;
            cp_tile(nb + 0 * TB, gAh, KO * 2, kb, tid);
            cp_tile(nb + 1 * TB, gAl, KO * 2, kb, tid);
            cp_tile(nb + 2 * TB, gBh, KO * 2, kb, tid);
            cp_tile(nb + 3 * TB, gBl, KO * 2, kb, tid);
            cp_commit();
            cp_wait1();
        } else {
            cp_wait0();
        }
        __syncthreads();
        compute_chunk(acc, buf, buf + TB, buf + 2 * TB, buf + 3 * TB, wm, wn, lane);
        __syncthreads();
    }
    const int g = lane >> 2, iq = lane & 3;
#pragma unroll
    for (int mt = 0; mt < 4; mt++) {
        int row = mBase + wm * 64 + mt * 16 + g;
        float* y0 = d_y + ((size_t)cidx * BATCH + row) * SEQ;
        float* y1 = y0 + 8 * (size_t)SEQ;
#pragma unroll
        for (int nt = 0; nt < 4; nt++) {
            int col = nBase + wn * 32 + nt * 8 + 2 * iq;
            if (col < SEQ) {
                float* cc = acc[mt][nt];
                *(float2*)(y0 + col) = make_float2(cc[0], cc[1]);
                *(float2*)(y1 + col) = make_float2(cc[2], cc[3]);
            }
        }
    }
}

// ---------------- transpose out: y[c][b][t] -> out[b][t][c], de-norm ---------
__global__ void k_transpose_out(float* __restrict__ out) {
    __shared__ float sm[32][33];
    int b = blockIdx.z;
    int c0 = blockIdx.x * 32, t0 = blockIdx.y * 32;
    int tx = threadIdx.x, ty = threadIdx.y;
#pragma unroll
    for (int i = 0; i < 4; i++) {
        int c = c0 + ty + i * 8;
        int t = t0 + tx;
        float v = 0.f;
        if (c < CH && t < SEQ)
            v = d_y[((size_t)c * BATCH + b) * SEQ + t];
        sm[ty + i * 8][tx] = v;
    }
    __syncthreads();
#pragma unroll
    for (int i = 0; i < 4; i++) {
        int t = t0 + ty + i * 8;
        int c = c0 + tx;
        if (t < SEQ && c < CH) {
            float v = sm[tx][ty + i * 8];
            out[(size_t)b * SEQ * CH + (size_t)t * CH + c] =
                v * d_stdev[b * CH + c] + d_mean[b * CH + c];
        }
    }
}

// ---------------- launch -----------------------------------------------------
extern "C" void kernel_launch(void* const* d_in, const int* in_sizes, int n_in,
                              void* d_out, int out_size) {
    const float* x_enc = (const float*)d_in[0];
    const float* Wr = (const float*)d_in[4];
    const float* Wi = (const float*)d_in[5];
    const float* br = (const float*)d_in[6];
    const float* bi = (const float*)d_in[7];
    float* out = (float*)d_out;

    static int attrDone = 0;
    if (!attrDone) {
        cudaFuncSetAttribute(k_g1, cudaFuncAttributeMaxDynamicSharedMemorySize, SMEM_BYTES);
        cudaFuncSetAttribute(k_g2, cudaFuncAttributeMaxDynamicSharedMemorySize, SMEM_BYTES);
        cudaFuncSetAttribute(k_g3, cudaFuncAttributeMaxDynamicSharedMemorySize, SMEM_BYTES);
        attrDone = 1;
    }

    k_init<<<1125, 256>>>();
    k_stats<<<dim3(2, BATCH), 256>>>(x_enc);
    k_transpose_in<<<dim3(11, 23, BATCH), dim3(32, 8)>>>(x_enc);
    k_g1<<<dim3(4, 2, CH), 256, SMEM_BYTES>>>();
    k_g2<<<dim3(7, 2, CH), 256, SMEM_BYTES>>>(Wr, Wi, br, bi);
    k_g3<<<dim3(6, 2, CH), 256, SMEM_BYTES>>>();
    k_transpose_out<<<dim3(11, 23, BATCH), dim3(32, 8)>>>(out);
}

// round 7
// speedup vs baseline: 5.8004x; 1.3917x over previous
#include <cuda_runtime.h>
#include <cuda_fp16.h>
#include <math.h>
#include <stdint.h>

#define BATCH 256
#define SEQ   720
#define CH    321
#define CUTF  200
#define FOUT  400

#define KD 768    // padded K stage1 (time 720)
#define KX 448    // padded K stage2 (2*CUTF=400)
#define KO 832    // padded K stage3 (2*FOUT=800)
#define N1 512    // padded N stage1
#define N3 768    // padded N stage3

#define RSB 80            // smem row stride bytes (32 fp16 + 16 pad)
#define TB  (128 * RSB)   // one tile: 10240 B
#define SMEM_BYTES (6 * TB)  // 2 buffers x 3 tiles = 61440

typedef unsigned int u32;
typedef uint16_t u16;

// ---------------- device scratch ---------------------------------------------
__device__ __align__(256) __half d_Eh[(size_t)N1 * KD];   // twiddle hi
__device__ __align__(256) __half d_El[(size_t)N1 * KD];   // twiddle lo
__device__ __align__(256) __half d_Fh[(size_t)N3 * KO];
__device__ __align__(256) __half d_Fl[(size_t)N3 * KO];
__device__ __align__(256) __half d_xn[(size_t)CH * BATCH * KD];   // normalized input
__device__ __align__(256) __half d_X[(size_t)CH * BATCH * KX];    // DFT out (interleaved re/im)
__device__ __align__(256) __half d_O[(size_t)CH * BATCH * KO];    // mixer out
__device__ __align__(256) float d_y[(size_t)CH * BATCH * SEQ];
__device__ float d_mean[BATCH * CH];
__device__ float d_stdev[BATCH * CH];
__device__ float d_invstd[BATCH * CH];

// ---------------- helpers ----------------------------------------------------
__device__ __forceinline__ u32 s2u(const void* p) {
    u32 a;
    asm("{ .reg .u64 t; cvta.to.shared.u64 t, %1; cvt.u32.u64 %0, t; }" : "=r"(a) : "l"(p));
    return a;
}
__device__ __forceinline__ void cpa16(u32 dst, const void* src) {
    asm volatile("cp.async.ca.shared.global [%0], [%1], 16;" :: "r"(dst), "l"(src));
}
__device__ __forceinline__ void cp_commit() { asm volatile("cp.async.commit_group;"); }
__device__ __forceinline__ void cp_wait1() { asm volatile("cp.async.wait_group 1;"); }
__device__ __forceinline__ void cp_wait0() { asm volatile("cp.async.wait_group 0;"); }
__device__ __forceinline__ void ldsm4(u32 a[4], u32 addr) {
    asm volatile("ldmatrix.sync.aligned.m8n8.x4.shared.b16 {%0,%1,%2,%3}, [%4];"
                 : "=r"(a[0]), "=r"(a[1]), "=r"(a[2]), "=r"(a[3]) : "r"(addr));
}
__device__ __forceinline__ void mma16816(float c[4], const u32 a[4], u32 b0, u32 b1) {
    asm volatile(
        "mma.sync.aligned.m16n8k16.row.col.f32.f16.f16.f32 "
        "{%0,%1,%2,%3},{%4,%5,%6,%7},{%8,%9},{%0,%1,%2,%3};"
        : "+f"(c[0]), "+f"(c[1]), "+f"(c[2]), "+f"(c[3])
        : "r"(a[0]), "r"(a[1]), "r"(a[2]), "r"(a[3]), "r"(b0), "r"(b1));
}
__device__ __forceinline__ u16 f2h(float v) { return __half_as_ushort(__float2half_rn(v)); }
__device__ __forceinline__ u32 pack2(float a, float b) {
    return (u32)f2h(a) | ((u32)f2h(b) << 16);
}

// cp.async one 128x32fp16 tile (64B/row) into padded smem
__device__ __forceinline__ void cp_tile(u32 smDst, const char* gSrc, int rowStrideBytes,
                                        int kByteOff, int tid) {
    int row = tid >> 1, seg = (tid & 1) * 32;
    const char* s = gSrc + (size_t)row * rowStrideBytes + kByteOff + seg;
    u32 d = smDst + row * RSB + seg;
    cpa16(d, s);
    cpa16(d + 16, s + 16);
}

// one 32-K chunk, 2-product fp16: A single, B hi+lo; nv = valid cols in tile
__device__ __forceinline__ void compute_chunk(float acc[4][4][4], u32 a_b,
                                              u32 bh_b, u32 bl_b,
                                              int wm, int wn, int lane, int nv) {
    if (wn * 32 >= nv) return;           // whole warp dead (warp-uniform)
    const int rsel = lane & 15;
    const int kbh = (lane >> 4) * 16;
#pragma unroll
    for (int k16 = 0; k16 < 2; k16++) {
        const int kb = k16 * 32 + kbh;
        u32 bh[2][4], bl[2][4];
#pragma unroll
        for (int np = 0; np < 2; np++) {
            if (wn * 32 + np * 16 < nv) {
                u32 off = (u32)(wn * 32 + np * 16 + rsel) * RSB + kb;
                ldsm4(bh[np], bh_b + off);
                ldsm4(bl[np], bl_b + off);
            }
        }
        u32 a[2][4];
        ldsm4(a[0], a_b + (u32)(wm * 64 + rsel) * RSB + kb);
#pragma unroll
        for (int mt = 0; mt < 4; mt++) {
            if (mt < 3)
                ldsm4(a[(mt + 1) & 1], a_b + (u32)(wm * 64 + (mt + 1) * 16 + rsel) * RSB + kb);
            const u32* av = a[mt & 1];
#pragma unroll
            for (int nt = 0; nt < 4; nt++) {
                if (wn * 32 + nt * 8 < nv) {
                    u32 b0h = bh[nt >> 1][nt & 1], b1h = bh[nt >> 1][(nt & 1) + 2];
                    u32 b0l = bl[nt >> 1][nt & 1], b1l = bl[nt >> 1][(nt & 1) + 2];
                    mma16816(acc[mt][nt], av, b0h, b1h);
                    mma16816(acc[mt][nt], av, b0l, b1l);
                }
            }
        }
    }
}

// ---------------- table init (fp16 hi/lo, exact integer phase) ---------------
__global__ void k_init() {
    int idx = blockIdx.x * 256 + threadIdx.x;
    if (idx < CUTF * SEQ) {
        int f = idx / SEQ, t = idx - f * SEQ;
        int r = (f * t) % SEQ;
        float s, cc;
        sincospif((float)r * (1.0f / 360.0f), &s, &cc);
        size_t i0 = (size_t)(2 * f) * KD + t;
        size_t i1 = (size_t)(2 * f + 1) * KD + t;
        __half h0 = __float2half_rn(cc);
        d_Eh[i0] = h0; d_El[i0] = __float2half_rn(cc - __half2float(h0));
        __half h1 = __float2half_rn(-s);
        d_Eh[i1] = h1; d_El[i1] = __float2half_rn(-s - __half2float(h1));
    }
    if (idx < SEQ * FOUT) {
        int tp = idx / FOUT, k = idx - tp * FOUT;
        int t = SEQ + tp;
        int m = (k * t) % 1440;
        float s, cc;
        sincospif((float)m * (1.0f / 720.0f), &s, &cc);
        float fc = (k == 0) ? (1.0f / 720.0f) : (cc * (1.0f / 360.0f));
        float fs = (k == 0) ? 0.0f : (-s * (1.0f / 360.0f));
        size_t i0 = (size_t)tp * KO + 2 * k;
        __half h0 = __float2half_rn(fc);
        d_Fh[i0] = h0; d_Fl[i0] = __float2half_rn(fc - __half2float(h0));
        __half h1 = __float2half_rn(fs);
        d_Fh[i0 + 1] = h1; d_Fl[i0 + 1] = __float2half_rn(fs - __half2float(h1));
    }
}

// ---------------- stats ------------------------------------------------------
__global__ void k_stats(const float* __restrict__ x) {
    int c = blockIdx.x * 256 + threadIdx.x;
    int b = blockIdx.y;
    if (c >= CH) return;
    const float* p = x + (size_t)b * SEQ * CH + c;
    float s = 0.f, ss = 0.f;
    for (int t = 0; t < SEQ; t++) {
        float v = p[(size_t)t * CH];
        s += v;
        ss += v * v;
    }
    float mean = s * (1.0f / SEQ);
    float var = (ss - s * mean) * (1.0f / (SEQ - 1));
    float sd = sqrtf(var + 1e-5f);
    d_mean[b * CH + c] = mean;
    d_stdev[b * CH + c] = sd;
    d_invstd[b * CH + c] = 1.0f / sd;
}

// ---------------- transpose in: x[b][t][c] -> xn[c][b][t] fp16 ---------------
__global__ void k_transpose_in(const float* __restrict__ x) {
    __shared__ float sm[32][33];
    int b = blockIdx.z;
    int c0 = blockIdx.x * 32, t0 = blockIdx.y * 32;
    int tx = threadIdx.x, ty = threadIdx.y;
#pragma unroll
    for (int i = 0; i < 4; i++) {
        int t = t0 + ty + i * 8, c = c0 + tx;
        float v = 0.f;
        if (c < CH && t < SEQ)
            v = (x[(size_t)b * SEQ * CH + (size_t)t * CH + c] - d_mean[b * CH + c]) * d_invstd[b * CH + c];
        sm[ty + i * 8][tx] = v;
    }
    __syncthreads();
#pragma unroll
    for (int i = 0; i < 4; i++) {
        int c = c0 + ty + i * 8;
        int t = t0 + tx;
        if (c < CH && t < SEQ)
            d_xn[((size_t)c * BATCH + b) * KD + t] = __float2half_rn(sm[tx][ty + i * 8]);
    }
}

// ---------------- stage 1: DFT GEMM ------------------------------------------
#define NCH1 23
__global__ __launch_bounds__(256, 2) void k_g1() {
    extern __shared__ char smraw[];
    u32 smb = s2u(smraw);
    const int tid = threadIdx.x, lane = tid & 31, warp = tid >> 5;
    const int wm = warp >> 2, wn = warp & 3;
    const int cidx = blockIdx.z, mBase = blockIdx.y * 128, nBase = blockIdx.x * 128;
    const int nv = 400 - nBase > 128 ? 128 : 400 - nBase;
    const char* gA = (const char*)(d_xn + ((size_t)cidx * BATCH + mBase) * KD);
    const char* gBh = (const char*)(d_Eh + (size_t)nBase * KD);
    const char* gBl = (const char*)(d_El + (size_t)nBase * KD);
    float acc[4][4][4] = {};

    cp_tile(smb + 0 * TB, gA, KD * 2, 0, tid);
    cp_tile(smb + 1 * TB, gBh, KD * 2, 0, tid);
    cp_tile(smb + 2 * TB, gBl, KD * 2, 0, tid);
    cp_commit();
    for (int ch = 0; ch < NCH1; ch++) {
        u32 buf = smb + (ch & 1) * 3 * TB;
        if (ch + 1 < NCH1) {
            u32 nb = smb + ((ch + 1) & 1) * 3 * TB;
            int kb = (ch + 1) * 64;
            cp_tile(nb + 0 * TB, gA, KD * 2, kb, tid);
            cp_tile(nb + 1 * TB, gBh, KD * 2, kb, tid);
            cp_tile(nb + 2 * TB, gBl, KD * 2, kb, tid);
            cp_commit();
            cp_wait1();
        } else {
            cp_wait0();
        }
        __syncthreads();
        compute_chunk(acc, buf, buf + TB, buf + 2 * TB, wm, wn, lane, nv);
        __syncthreads();
    }
    const int g = lane >> 2, iq = lane & 3;
#pragma unroll
    for (int mt = 0; mt < 4; mt++) {
        int row = mBase + wm * 64 + mt * 16 + g;
        size_t b0 = ((size_t)cidx * BATCH + row) * KX;
        size_t b1 = b0 + 8 * (size_t)KX;
#pragma unroll
        for (int nt = 0; nt < 4; nt++) {
            int col = nBase + wn * 32 + nt * 8 + 2 * iq;
            if (col < 400) {
                float* cc = acc[mt][nt];
                *(u32*)(d_X + b0 + col) = pack2(cc[0], cc[1]);
                *(u32*)(d_X + b1 + col) = pack2(cc[2], cc[3]);
            }
        }
    }
}

// ---------------- stage 2: complex mixer GEMM --------------------------------
// build W2 chunk (128 o2-rows x 32 k2-cols) hi/lo fp16 into smem
__device__ __forceinline__ void build_w2(const float* __restrict__ Wr,
                                         const float* __restrict__ Wi,
                                         int cidx, int nBase, int chunk,
                                         u32 Bh, u32 Bl, int tid) {
    int oloc = tid >> 2;            // 0..63
    int part = tid & 3;             // 4 f values each
    int o = (nBase >> 1) + oloc;
    int f0 = chunk * 16 + part * 4;
    float av[4] = {0.f, 0.f, 0.f, 0.f}, qv[4] = {0.f, 0.f, 0.f, 0.f};
    if (o < FOUT) {
        const float* wr = Wr + ((size_t)cidx * FOUT + o) * CUTF;
        const float* wi = Wi + ((size_t)cidx * FOUT + o) * CUTF;
        if (f0 + 3 < CUTF) {
            float4 wr4 = *(const float4*)(wr + f0);
            float4 wi4 = *(const float4*)(wi + f0);
            av[0] = wr4.x; av[1] = wr4.y; av[2] = wr4.z; av[3] = wr4.w;
            qv[0] = wi4.x; qv[1] = wi4.y; qv[2] = wi4.z; qv[3] = wi4.w;
        } else {
#pragma unroll
            for (int j = 0; j < 4; j++)
                if (f0 + j < CUTF) { av[j] = wr[f0 + j]; qv[j] = wi[f0 + j]; }
        }
    }
    u32 he[4], le[4], ho[4], lo[4];
#pragma unroll
    for (int j = 0; j < 4; j++) {
        // even row (p=0): (wr, -wi) ; odd row (p=1): (wi, wr)
        float e0 = av[j], e1 = -qv[j];
        float o0 = qv[j], o1 = av[j];
        __half e0h = __float2half_rn(e0), e1h = __float2half_rn(e1);
        __half o0h = __float2half_rn(o0), o1h = __float2half_rn(o1);
        he[j] = (u32)__half_as_ushort(e0h) | ((u32)__half_as_ushort(e1h) << 16);
        ho[j] = (u32)__half_as_ushort(o0h) | ((u32)__half_as_ushort(o1h) << 16);
        le[j] = pack2(e0 - __half2float(e0h), e1 - __half2float(e1h));
        lo[j] = pack2(o0 - __half2float(o0h), o1 - __half2float(o1h));
    }
    u32 offE = (u32)(2 * oloc) * RSB + part * 16;
    u32 offO = offE + RSB;
    asm volatile("st.shared.v4.b32 [%0], {%1,%2,%3,%4};" :: "r"(Bh + offE), "r"(he[0]), "r"(he[1]), "r"(he[2]), "r"(he[3]));
    asm volatile("st.shared.v4.b32 [%0], {%1,%2,%3,%4};" :: "r"(Bl + offE), "r"(le[0]), "r"(le[1]), "r"(le[2]), "r"(le[3]));
    asm volatile("st.shared.v4.b32 [%0], {%1,%2,%3,%4};" :: "r"(Bh + offO), "r"(ho[0]), "r"(ho[1]), "r"(ho[2]), "r"(ho[3]));
    asm volatile("st.shared.v4.b32 [%0], {%1,%2,%3,%4};" :: "r"(Bl + offO), "r"(lo[0]), "r"(lo[1]), "r"(lo[2]), "r"(lo[3]));
}

#define NCH2 13
__global__ __launch_bounds__(256, 2) void k_g2(const float* __restrict__ Wr,
                                               const float* __restrict__ Wi,
                                               const float* __restrict__ br,
                                               const float* __restrict__ bi) {
    extern __shared__ char smraw[];
    u32 smb = s2u(smraw);
    const int tid = threadIdx.x, lane = tid & 31, warp = tid >> 5;
    const int wm = warp >> 2, wn = warp & 3;
    const int cidx = blockIdx.z, mBase = blockIdx.y * 128, nBase = blockIdx.x * 128;
    const int nv = 800 - nBase > 128 ? 128 : 800 - nBase;
    const char* gA = (const char*)(d_X + ((size_t)cidx * BATCH + mBase) * KX);
    float acc[4][4][4] = {};

    cp_tile(smb + 0 * TB, gA, KX * 2, 0, tid);
    cp_commit();
    build_w2(Wr, Wi, cidx, nBase, 0, smb + 1 * TB, smb + 2 * TB, tid);
    for (int ch = 0; ch < NCH2; ch++) {
        u32 buf = smb + (ch & 1) * 3 * TB;
        if (ch + 1 < NCH2) {
            u32 nb = smb + ((ch + 1) & 1) * 3 * TB;
            cp_tile(nb + 0 * TB, gA, KX * 2, (ch + 1) * 64, tid);
            cp_commit();
            build_w2(Wr, Wi, cidx, nBase, ch + 1, nb + 1 * TB, nb + 2 * TB, tid);
            cp_wait1();
        } else {
            cp_wait0();
        }
        __syncthreads();
        compute_chunk(acc, buf, buf + TB, buf + 2 * TB, wm, wn, lane, nv);
        __syncthreads();
    }
    const int g = lane >> 2, iq = lane & 3;
    const float* brp = br + (size_t)cidx * FOUT;
    const float* bip = bi + (size_t)cidx * FOUT;
#pragma unroll
    for (int mt = 0; mt < 4; mt++) {
        int row = mBase + wm * 64 + mt * 16 + g;
        size_t b0 = ((size_t)cidx * BATCH + row) * KO;
        size_t b1 = b0 + 8 * (size_t)KO;
#pragma unroll
        for (int nt = 0; nt < 4; nt++) {
            int col = nBase + wn * 32 + nt * 8 + 2 * iq;
            if (col < 800) {
                int o = col >> 1;
                float vr = brp[o], vi = bip[o];
                float* cc = acc[mt][nt];
                *(u32*)(d_O + b0 + col) = pack2(cc[0] + vr, cc[1] + vi);
                *(u32*)(d_O + b1 + col) = pack2(cc[2] + vr, cc[3] + vi);
            }
        }
    }
}

// ---------------- stage 3: irfft GEMM ----------------------------------------
#define NCH3 25
__global__ __launch_bounds__(256, 2) void k_g3() {
    extern __shared__ char smraw[];
    u32 smb = s2u(smraw);
    const int tid = threadIdx.x, lane = tid & 31, warp = tid >> 5;
    const int wm = warp >> 2, wn = warp & 3;
    const int cidx = blockIdx.z, mBase = blockIdx.y * 128, nBase = blockIdx.x * 128;
    const int nv = 720 - nBase > 128 ? 128 : 720 - nBase;
    const char* gA = (const char*)(d_O + ((size_t)cidx * BATCH + mBase) * KO);
    const char* gBh = (const char*)(d_Fh + (size_t)nBase * KO);
    const char* gBl = (const char*)(d_Fl + (size_t)nBase * KO);
    float acc[4][4][4] = {};

    cp_tile(smb + 0 * TB, gA, KO * 2, 0, tid);
    cp_tile(smb + 1 * TB, gBh, KO * 2, 0, tid);
    cp_tile(smb + 2 * TB, gBl, KO * 2, 0, tid);
    cp_commit();
    for (int ch = 0; ch < NCH3; ch++) {
        u32 buf = smb + (ch & 1) * 3 * TB;
        if (ch + 1 < NCH3) {
            u32 nb = smb + ((ch + 1) & 1) * 3 * TB;
            int kb = (ch + 1) * 64;
            cp_tile(nb + 0 * TB, gA, KO * 2, kb, tid);
            cp_tile(nb + 1 * TB, gBh, KO * 2, kb, tid);
            cp_tile(nb + 2 * TB, gBl, KO * 2, kb, tid);
            cp_commit();
            cp_wait1();
        } else {
            cp_wait0();
        }
        __syncthreads();
        compute_chunk(acc, buf, buf + TB, buf + 2 * TB, wm, wn, lane, nv);
        __syncthreads();
    }
    const int g = lane >> 2, iq = lane & 3;
#pragma unroll
    for (int mt = 0; mt < 4; mt++) {
        int row = mBase + wm * 64 + mt * 16 + g;
        float* y0 = d_y + ((size_t)cidx * BATCH + row) * SEQ;
        float* y1 = y0 + 8 * (size_t)SEQ;
#pragma unroll
        for (int nt = 0; nt < 4; nt++) {
            int col = nBase + wn * 32 + nt * 8 + 2 * iq;
            if (col < SEQ) {
                float* cc = acc[mt][nt];
                *(float2*)(y0 + col) = make_float2(cc[0], cc[1]);
                *(float2*)(y1 + col) = make_float2(cc[2], cc[3]);
            }
        }
    }
}

// ---------------- transpose out: y[c][b][t] -> out[b][t][c], de-norm ---------
__global__ void k_transpose_out(float* __restrict__ out) {
    __shared__ float sm[32][33];
    int b = blockIdx.z;
    int c0 = blockIdx.x * 32, t0 = blockIdx.y * 32;
    int tx = threadIdx.x, ty = threadIdx.y;
#pragma unroll
    for (int i = 0; i < 4; i++) {
        int c = c0 + ty + i * 8;
        int t = t0 + tx;
        float v = 0.f;
        if (c < CH && t < SEQ)
            v = d_y[((size_t)c * BATCH + b) * SEQ + t];
        sm[ty + i * 8][tx] = v;
    }
    __syncthreads();
#pragma unroll
    for (int i = 0; i < 4; i++) {
        int t = t0 + ty + i * 8;
        int c = c0 + tx;
        if (t < SEQ && c < CH) {
            float v = sm[tx][ty + i * 8];
            out[(size_t)b * SEQ * CH + (size_t)t * CH + c] =
                v * d_stdev[b * CH + c] + d_mean[b * CH + c];
        }
    }
}

// ---------------- launch -----------------------------------------------------
extern "C" void kernel_launch(void* const* d_in, const int* in_sizes, int n_in,
                              void* d_out, int out_size) {
    const float* x_enc = (const float*)d_in[0];
    const float* Wr = (const float*)d_in[4];
    const float* Wi = (const float*)d_in[5];
    const float* br = (const float*)d_in[6];
    const float* bi = (const float*)d_in[7];
    float* out = (float*)d_out;

    static int attrDone = 0;
    if (!attrDone) {
        cudaFuncSetAttribute(k_g1, cudaFuncAttributeMaxDynamicSharedMemorySize, SMEM_BYTES);
        cudaFuncSetAttribute(k_g2, cudaFuncAttributeMaxDynamicSharedMemorySize, SMEM_BYTES);
        cudaFuncSetAttribute(k_g3, cudaFuncAttributeMaxDynamicSharedMemorySize, SMEM_BYTES);
        attrDone = 1;
    }

    k_init<<<1125, 256>>>();
    k_stats<<<dim3(2, BATCH), 256>>>(x_enc);
    k_transpose_in<<<dim3(11, 23, BATCH), dim3(32, 8)>>>(x_enc);
    k_g1<<<dim3(4, 2, CH), 256, SMEM_BYTES>>>();
    k_g2<<<dim3(7, 2, CH), 256, SMEM_BYTES>>>(Wr, Wi, br, bi);
    k_g3<<<dim3(6, 2, CH), 256, SMEM_BYTES>>>();
    k_transpose_out<<<dim3(11, 23, BATCH), dim3(32, 8)>>>(out);
}